// round 7
// baseline (speedup 1.0000x reference)
#include <cuda_runtime.h>
#include <math.h>

// Shape fixed by reference: x,y = [16, 3, 512, 512] f32
#define BATCH   16
#define HDIM    512
#define WDIM    512
#define RSTRIP  64                    // output rows per block
#define STRIPS  (HDIM / RSTRIP)       // 8
#define CSPLIT  2                     // column tiles per image
#define CTILE   (WDIM / CSPLIT)       // 256
#define NBLOCKS (BATCH * STRIPS * CSPLIT)  // 256
#define THREADS 256
#define RGROUPS 4                     // row-groups of 64 lanes
#define LANES   64                    // float4 lanes per row
#define ROWSIN  (RSTRIP + 6)          // 70 input rows incl. vertical halo
#define CHUNKS  ((ROWSIN + RGROUPS - 1) / RGROUPS)  // 18 (covers idx 0..71)
#define HROWS   (CHUNKS * RGROUPS)    // 72 (halo array size)
#define EPSV    1e-6f

__device__ float        g_partials[NBLOCKS];
__device__ unsigned int g_count;     // zero-init at load; reset by last block

__device__ __forceinline__ void rg_barrier(int rg) {
    // 64-thread named barrier per row-group (ids 1..4; 0 is __syncthreads)
    asm volatile("bar.sync %0, %1;" :: "r"(rg + 1), "r"(64) : "memory");
}

__global__ __launch_bounds__(THREADS, 3) void charb_kernel(
    const float* __restrict__ x, const float* __restrict__ y,
    float* __restrict__ out)
{
    __shared__ float drow[RGROUPS][264]; // diff row: [0..3]=L halo, [4..259]=main, [260..263]=R halo
    __shared__ float hs[16][CTILE];      // ring of horizontal 7-tap sums
    __shared__ float hl[HROWS][4];       // left seam diff per stream row
    __shared__ float hr[HROWS][4];       // right seam diff per stream row
    __shared__ float warpsum[THREADS / 32];
    __shared__ bool  isLast;

    const int tid  = threadIdx.x;
    const int rg   = tid >> 6;         // row-group 0..3
    const int c4   = tid & 63;         // float4 lane within row
    const int col0 = c4 << 2;          // local col 0..252

    const int blk = blockIdx.x;
    const int b   = blk >> 4;                  // batch
    const int rem = blk & 15;
    const int s   = rem >> 1;                  // strip 0..7
    const int ct  = rem & 1;                   // column tile 0..1
    const int h0  = s * RSTRIP;
    const int cb  = ct * CTILE;

    const size_t plane = (size_t)HDIM * WDIM;
    const float* xb = x + (size_t)b * 3 * plane;
    const float* yb = y + (size_t)b * 3 * plane;

    // ---- prologue: stage seam (horizontal halo) diffs into smem ----
    // real seam: ct==0 -> cols 256..259 (right); ct==1 -> cols 252..255 (left)
    {
        const int hcol = (ct == 0) ? CTILE : (CTILE - 4);   // global col = cb + hcol... see below
        if (tid < HROWS) {
            const int rr = tid;
            const int r  = h0 - 3 + rr;
            float4 v = make_float4(0.f, 0.f, 0.f, 0.f);
            if (rr < ROWSIN && r >= 0 && r < HDIM) {
                const int gc = cb + hcol;      // ct0: 256..259, ct1: 252+256=508?? no:
                // ct==0: seam cols = 256..259 = cb(0)+256.  ct==1: seam cols = 252..255 = cb(256)-4.
                const int gcc = (ct == 0) ? (CTILE) : (CTILE - 4 + 0) ; (void)gc; (void)gcc;
                const int gcol = (ct == 0) ? (cb + CTILE) : (cb - 4);
                const float* xp = xb + (size_t)r * WDIM + gcol;
                const float* yp = yb + (size_t)r * WDIM + gcol;
                const float4 a0 = *(const float4*)(xp);
                const float4 a1 = *(const float4*)(xp + plane);
                const float4 a2 = *(const float4*)(xp + 2 * plane);
                const float4 q0 = *(const float4*)(yp);
                const float4 q1 = *(const float4*)(yp + plane);
                const float4 q2 = *(const float4*)(yp + 2 * plane);
                v.x = (a0.x - q0.x) + (a1.x - q1.x) + (a2.x - q2.x);
                v.y = (a0.y - q0.y) + (a1.y - q1.y) + (a2.y - q2.y);
                v.z = (a0.z - q0.z) + (a1.z - q1.z) + (a2.z - q2.z);
                v.w = (a0.w - q0.w) + (a1.w - q1.w) + (a2.w - q2.w);
            }
            if (ct == 0) *(float4*)hr[rr] = v;   // right seam real
            else         *(float4*)hl[rr] = v;   // left seam real
        } else if (tid >= 128 && tid < 128 + HROWS) {
            const int rr = tid - 128;            // zero the off-image side
            if (ct == 0) *(float4*)hl[rr] = make_float4(0.f, 0.f, 0.f, 0.f);
            else         *(float4*)hr[rr] = make_float4(0.f, 0.f, 0.f, 0.f);
        }
    }

    // ---- prologue: pipelined load of chunk 0 ----
    const float4 z4 = make_float4(0.f, 0.f, 0.f, 0.f);
    float4 a0 = z4, a1 = z4, a2 = z4, q0 = z4, q1 = z4, q2 = z4;
    bool valid;
    {
        const int r = h0 - 3 + rg;
        valid = (r >= 0) && (r < HDIM);
        if (valid) {
            const float* xp = xb + (size_t)r * WDIM + cb + col0;
            const float* yp = yb + (size_t)r * WDIM + cb + col0;
            a0 = *(const float4*)(xp);
            a1 = *(const float4*)(xp + plane);
            a2 = *(const float4*)(xp + 2 * plane);
            q0 = *(const float4*)(yp);
            q1 = *(const float4*)(yp + plane);
            q2 = *(const float4*)(yp + 2 * plane);
        }
    }
    __syncthreads();   // hl/hr staged

    float acc = 0.f;

    #pragma unroll 1
    for (int ch = 0; ch < CHUNKS; ++ch) {
        const int idx = ch * RGROUPS + rg;   // row index within strip stream

        // channel-summed diff -> smem main slots
        float4 d = z4;
        if (valid) {
            d.x = (a0.x - q0.x) + (a1.x - q1.x) + (a2.x - q2.x);
            d.y = (a0.y - q0.y) + (a1.y - q1.y) + (a2.y - q2.y);
            d.z = (a0.z - q0.z) + (a1.z - q1.z) + (a2.z - q2.z);
            d.w = (a0.w - q0.w) + (a1.w - q1.w) + (a2.w - q2.w);
        }
        *(float4*)&drow[rg][4 + col0] = d;
        if (c4 == 0)  *(float4*)&drow[rg][0]   = *(const float4*)hl[idx];
        if (c4 == 63) *(float4*)&drow[rg][260] = *(const float4*)hr[idx];

        // prefetch next chunk
        {
            const int nidx = idx + RGROUPS;
            const int nr   = h0 - 3 + nidx;
            valid = (nidx < ROWSIN) && (nr >= 0) && (nr < HDIM);
            if (valid) {
                const float* xp = xb + (size_t)nr * WDIM + cb + col0;
                const float* yp = yb + (size_t)nr * WDIM + cb + col0;
                a0 = *(const float4*)(xp);
                a1 = *(const float4*)(xp + plane);
                a2 = *(const float4*)(xp + 2 * plane);
                q0 = *(const float4*)(yp);
                q1 = *(const float4*)(yp + plane);
                q2 = *(const float4*)(yp + 2 * plane);
            }
        }

        rg_barrier(rg);                 // drow ready within this row-group

        // horizontal 7-tap sums via 3 aligned LDS.128
        float f[12];
        *(float4*)&f[0] = *(const float4*)&drow[rg][col0];
        *(float4*)&f[4] = *(const float4*)&drow[rg][col0 + 4];
        *(float4*)&f[8] = *(const float4*)&drow[rg][col0 + 8];
        const float s0 = ((f[1] + f[2]) + (f[3] + f[4])) + ((f[5] + f[6]) + f[7]);
        const float s1 = s0 - f[1] + f[8];
        const float s2 = s1 - f[2] + f[9];
        const float s3 = s2 - f[3] + f[10];
        *(float4*)&hs[idx & 15][col0] = make_float4(s0, s1, s2, s3);

        __syncthreads();                // hs rows from all row-groups visible
                                        // (ring WAR safe: span of live slots <= 10 < 16)

        // vertical 7-tap + Charbonnier for output row o = idx - 6
        const int o = idx - 6;
        if (o >= 0 && o < RSTRIP) {
            float4 v = *(const float4*)&hs[o & 15][col0];
            #pragma unroll
            for (int t = 1; t < 7; ++t) {
                const float4 hv = *(const float4*)&hs[(o + t) & 15][col0];
                v.x += hv.x; v.y += hv.y; v.z += hv.z; v.w += hv.w;
            }
            const float inv = 1.f / 49.f;
            v.x *= inv; v.y *= inv; v.z *= inv; v.w *= inv;
            acc += (sqrtf(v.x * v.x + EPSV) + sqrtf(v.y * v.y + EPSV))
                 + (sqrtf(v.z * v.z + EPSV) + sqrtf(v.w * v.w + EPSV));
        }
    }

    // block reduction
    #pragma unroll
    for (int off = 16; off; off >>= 1) acc += __shfl_xor_sync(0xffffffffu, acc, off);
    if ((tid & 31) == 0) warpsum[tid >> 5] = acc;
    __syncthreads();
    if (tid < 32) {
        float v = (tid < THREADS / 32) ? warpsum[tid] : 0.f;
        #pragma unroll
        for (int off = 4; off; off >>= 1) v += __shfl_xor_sync(0xffffffffu, v, off);
        if (tid == 0) {
            g_partials[blk] = v;
            __threadfence();
            const unsigned int t = atomicAdd(&g_count, 1u);
            isLast = (t == NBLOCKS - 1);
        }
    }
    __syncthreads();

    // last-arriving block folds the 256 partials -> scalar (deterministic order)
    if (isLast) {
        __threadfence();
        float v = (tid < NBLOCKS) ? g_partials[tid] : 0.f;
        #pragma unroll
        for (int off = 16; off; off >>= 1) v += __shfl_xor_sync(0xffffffffu, v, off);
        if ((tid & 31) == 0) warpsum[tid >> 5] = v;
        __syncthreads();
        if (tid < 32) {
            float v2 = (tid < THREADS / 32) ? warpsum[tid] : 0.f;
            #pragma unroll
            for (int off = 4; off; off >>= 1) v2 += __shfl_xor_sync(0xffffffffu, v2, off);
            if (tid == 0) {
                out[0]  = v2 / (float)((size_t)BATCH * HDIM * WDIM);
                g_count = 0u;
            }
        }
    }
}

extern "C" void kernel_launch(void* const* d_in, const int* in_sizes, int n_in,
                              void* d_out, int out_size)
{
    (void)in_sizes; (void)n_in; (void)out_size;
    const float* x = (const float*)d_in[0];
    const float* y = (const float*)d_in[1];
    float* out = (float*)d_out;

    charb_kernel<<<NBLOCKS, THREADS>>>(x, y, out);
}

// round 8
// speedup vs baseline: 1.0860x; 1.0860x over previous
#include <cuda_runtime.h>
#include <math.h>

// Shape fixed by reference: x,y = [16, 3, 512, 512] f32
#define BATCH   16
#define HDIM    512
#define WDIM    512
#define RSTRIP  16                    // output rows per block
#define STRIPS  (HDIM / RSTRIP)       // 32
#define NBLOCKS (BATCH * STRIPS)      // 512
#define RGROUPS 2                     // row-groups of 128 lanes
#define THREADS (RGROUPS * 128)       // 256
#define ROWSIN  (RSTRIP + 6)          // 22 input rows incl. halo
#define CHUNKS  (ROWSIN / RGROUPS)    // 11
#define EPSV    1e-6f

__device__ float        g_partials[NBLOCKS];
__device__ unsigned int g_count;     // zero-init at load; reset by last block

__device__ __forceinline__ void rg_barrier(int rg) {
    // 128-thread named barrier per row-group (ids 1..RGROUPS)
    asm volatile("bar.sync %0, %1;" :: "r"(rg + 1), "r"(128) : "memory");
}

__global__ __launch_bounds__(THREADS, 4) void charb_kernel(
    const float* __restrict__ x, const float* __restrict__ y,
    float* __restrict__ out)
{
    __shared__ float drow[RGROUPS][520]; // diff row, halo-padded (d[c] at [4+c])
    __shared__ float hs[16][WDIM];       // ring of horizontal 7-tap sums
    __shared__ float warpsum[THREADS / 32];
    __shared__ bool  isLast;

    const int tid  = threadIdx.x;
    const int rg   = tid >> 7;         // row-group 0..1
    const int c4   = tid & 127;        // float4 column index
    const int col0 = c4 << 2;

    const int blk = blockIdx.x;
    const int b   = blk / STRIPS;
    const int s   = blk % STRIPS;
    const int h0  = s * RSTRIP;
    const bool rev = (s & 1);          // serpentine: odd strips stream bottom-up

    if (c4 == 0) {                     // zero side halos once
        drow[rg][0] = drow[rg][1] = drow[rg][2] = drow[rg][3] = 0.f;
        drow[rg][516] = drow[rg][517] = drow[rg][518] = drow[rg][519] = 0.f;
    }

    const size_t plane = (size_t)HDIM * WDIM;
    const float* xb = x + (size_t)b * 3 * plane;
    const float* yb = y + (size_t)b * 3 * plane;

    // stream index i -> image row
    //   fwd: r = h0 - 3 + i          (i = 0..21)
    //   rev: r = h0 + RSTRIP + 2 - i
    const int rbase = rev ? (h0 + RSTRIP + 2) : (h0 - 3);
    const int rstep = rev ? -1 : 1;

    const float4 z4 = make_float4(0.f, 0.f, 0.f, 0.f);
    float4 a0 = z4, a1 = z4, a2 = z4, q0 = z4, q1 = z4, q2 = z4;
    bool valid;

    {   // prologue: load stream row i = rg
        const int r = rbase + rstep * rg;
        valid = (r >= 0) && (r < HDIM);
        if (valid) {
            const float* xp = xb + (size_t)r * WDIM + col0;
            const float* yp = yb + (size_t)r * WDIM + col0;
            a0 = *(const float4*)(xp);
            a1 = *(const float4*)(xp + plane);
            a2 = *(const float4*)(xp + 2 * plane);
            q0 = *(const float4*)(yp);
            q1 = *(const float4*)(yp + plane);
            q2 = *(const float4*)(yp + 2 * plane);
        }
    }

    float acc = 0.f;

    #pragma unroll 1
    for (int ch = 0; ch < CHUNKS; ++ch) {
        const int i = ch * RGROUPS + rg;   // stream index

        // channel-summed diff -> smem
        float4 d = z4;
        if (valid) {
            d.x = (a0.x - q0.x) + (a1.x - q1.x) + (a2.x - q2.x);
            d.y = (a0.y - q0.y) + (a1.y - q1.y) + (a2.y - q2.y);
            d.z = (a0.z - q0.z) + (a1.z - q1.z) + (a2.z - q2.z);
            d.w = (a0.w - q0.w) + (a1.w - q1.w) + (a2.w - q2.w);
        }
        *(float4*)&drow[rg][4 + col0] = d;

        // prefetch next stream row
        {
            const int ni = i + RGROUPS;
            const int nr = rbase + rstep * ni;
            valid = (ni < ROWSIN) && (nr >= 0) && (nr < HDIM);
            if (valid) {
                const float* xp = xb + (size_t)nr * WDIM + col0;
                const float* yp = yb + (size_t)nr * WDIM + col0;
                a0 = *(const float4*)(xp);
                a1 = *(const float4*)(xp + plane);
                a2 = *(const float4*)(xp + 2 * plane);
                q0 = *(const float4*)(yp);
                q1 = *(const float4*)(yp + plane);
                q2 = *(const float4*)(yp + 2 * plane);
            }
        }

        rg_barrier(rg);                 // drow ready within this row-group

        // horizontal 7-tap sums via 3 aligned LDS.128
        float f[12];
        *(float4*)&f[0] = *(const float4*)&drow[rg][col0];
        *(float4*)&f[4] = *(const float4*)&drow[rg][col0 + 4];
        *(float4*)&f[8] = *(const float4*)&drow[rg][col0 + 8];
        const float s0 = ((f[1] + f[2]) + (f[3] + f[4])) + ((f[5] + f[6]) + f[7]);
        const float s1 = s0 - f[1] + f[8];
        const float s2 = s1 - f[2] + f[9];
        const float s3 = s2 - f[3] + f[10];
        *(float4*)&hs[i & 15][col0] = make_float4(s0, s1, s2, s3);

        __syncthreads();                // hs rows from all row-groups visible
                                        // (ring WAR safe: live span <= 9 < 16)

        // vertical 7-tap + Charbonnier once a full 7-row window is streamed
        if (i >= 6) {
            const int o = i - 6;        // oldest slot of the window (ring index base)
            float4 v = *(const float4*)&hs[o & 15][col0];
            #pragma unroll
            for (int t = 1; t < 7; ++t) {
                const float4 hv = *(const float4*)&hs[(o + t) & 15][col0];
                v.x += hv.x; v.y += hv.y; v.z += hv.z; v.w += hv.w;
            }
            const float inv = 1.f / 49.f;
            v.x *= inv; v.y *= inv; v.z *= inv; v.w *= inv;
            acc += (sqrtf(v.x * v.x + EPSV) + sqrtf(v.y * v.y + EPSV))
                 + (sqrtf(v.z * v.z + EPSV) + sqrtf(v.w * v.w + EPSV));
        }
    }

    // block reduction
    #pragma unroll
    for (int off = 16; off; off >>= 1) acc += __shfl_xor_sync(0xffffffffu, acc, off);
    if ((tid & 31) == 0) warpsum[tid >> 5] = acc;
    __syncthreads();
    if (tid < 32) {
        float v = (tid < THREADS / 32) ? warpsum[tid] : 0.f;
        #pragma unroll
        for (int off = 4; off; off >>= 1) v += __shfl_xor_sync(0xffffffffu, v, off);
        if (tid == 0) {
            g_partials[blk] = v;
            __threadfence();
            const unsigned int t = atomicAdd(&g_count, 1u);
            isLast = (t == NBLOCKS - 1);
        }
    }
    __syncthreads();

    // last-arriving block folds the 512 partials -> scalar (deterministic order)
    if (isLast) {
        __threadfence();
        float v = g_partials[tid] + g_partials[tid + THREADS];
        #pragma unroll
        for (int off = 16; off; off >>= 1) v += __shfl_xor_sync(0xffffffffu, v, off);
        if ((tid & 31) == 0) warpsum[tid >> 5] = v;
        __syncthreads();
        if (tid < 32) {
            float v2 = (tid < THREADS / 32) ? warpsum[tid] : 0.f;
            #pragma unroll
            for (int off = 4; off; off >>= 1) v2 += __shfl_xor_sync(0xffffffffu, v2, off);
            if (tid == 0) {
                out[0]  = v2 / (float)((size_t)BATCH * HDIM * WDIM);
                g_count = 0u;
            }
        }
    }
}

extern "C" void kernel_launch(void* const* d_in, const int* in_sizes, int n_in,
                              void* d_out, int out_size)
{
    (void)in_sizes; (void)n_in; (void)out_size;
    const float* x = (const float*)d_in[0];
    const float* y = (const float*)d_in[1];
    float* out = (float*)d_out;

    charb_kernel<<<NBLOCKS, THREADS>>>(x, y, out);
}